// round 12
// baseline (speedup 1.0000x reference)
#include <cuda_runtime.h>

// Problem constants (fixed by the reference)
#define NN 32768
#define DD 32
#define HH 64
#define TT 1024
#define MM 8
#define SS 2177          // H*D + H + O*H + O
#define SROW 2208        // padded state row stride (floats)
#define CAP 128          // bucket capacity (Poisson(32); P(>128) ~ 0)
#define GRID 128         // all-resident on 148 SMs -> grid barrier is safe
#define BLOCK 512        // 16 warps: 8 t's x 2 INDEPENDENT j-half warps

// Scratch (no allocations allowed). Zero-initialized at module load; each
// launch restores the zeros it consumed (invariant across graph replays).
__device__ int g_cnt[TT];
__device__ int g_bucket[TT * CAP];
__device__ int g_ocnt;
__device__ int g_ovf[NN];
__device__ int g_arrive;
__device__ int g_epoch;     // monotonic across launches

// packed fp32x2 ops (Blackwell; ptxas never auto-fuses these)
#define FMA2(d, a, b, c) \
    asm("fma.rn.f32x2 %0, %1, %2, %3;" : "=l"(d) : "l"(a), "l"(b), "l"(c))
#define ADD2(d, a, b) \
    asm("add.rn.f32x2 %0, %1, %2;" : "=l"(d) : "l"(a), "l"(b))
#define PACK2(d, lo, hi) \
    asm("mov.b64 %0, {%1, %2};" : "=l"(d) : "f"(lo), "f"(hi))
#define UNPACK2(lo, hi, s) \
    asm("mov.b64 {%0, %1}, %2;" : "=f"(lo), "=f"(hi) : "l"(s))

// ---------------------------------------------------------------------------
// ONE fused persistent kernel.
//   Phase A: scatter n's into per-t buckets (first 256 threads) AND pre-seed
//            out[n] = b2(ticker[n]) (8 FMA) so phase C can use no-return
//            atomicAdd to combine j-halves.
//   Phase B: compute this block's 8 state rows straight into smem.
//   Global epoch barrier (all blocks resident; orders A stores before C).
//   Phase C: 2 independent warps per t, each owns 32 of the 64 hidden units;
//            lane = sample; per-lane direct LDG.128 x row; packed f32x2 FMA;
//            halves combined via REDG.F32 atomicAdd (exactly 2 adds/output,
//            order-invariant -> deterministic). NO inter-warp sync.
// ---------------------------------------------------------------------------
__global__ __launch_bounds__(BLOCK, 1)
void fused_k(const float* __restrict__ x,
             const int*   __restrict__ ticker,
             const float* __restrict__ mesa,
             const float* __restrict__ meta,
             const float* __restrict__ bias,
             const float* __restrict__ base,
             float*       __restrict__ out) {
    extern __shared__ float sm[];
    float* st      = sm;                    // 8 * SROW state rows (70.6 KB)
    float* sm_mesa = sm + 8 * SROW;         // 64 floats

    int tid  = threadIdx.x;
    int warp = tid >> 5, lane = tid & 31;
    int grp  = warp >> 1, sub = warp & 1;   // grp = t slot, sub = j half
    int t0   = blockIdx.x * 8;

    // ---- Phase A: scatter + out pre-seed (GRID*256 == NN exactly) ----
    if (tid < 256) {
        int n = blockIdx.x * 256 + tid;
        int t = ticker[n];
        int pos = atomicAdd(&g_cnt[t], 1);
        if (pos < CAP) g_bucket[t * CAP + pos] = n;
        else           g_ovf[atomicAdd(&g_ocnt, 1)] = n;

        // b2(t) = base[2176] + bias[2176] + sum_m mesa[m][t]*meta[2176][m]
        float b2 = base[2176] + bias[2176];
#pragma unroll
        for (int m = 0; m < MM; m++)
            b2 = fmaf(mesa[m * TT + t], __ldg(meta + 2176 * MM + m), b2);
        out[n] = b2;
    }

    // ---- Phase B: states for my 8 t's, directly in smem ----
    if (tid < 64)
        sm_mesa[tid] = mesa[(tid >> 3) * TT + t0 + (tid & 7)];
    __syncthreads();

    for (int s = tid; s < SS; s += BLOCK) {
        const float4* mp = (const float4*)(meta + s * MM);
        float4 m0 = mp[0], m1 = mp[1];      // meta[s][0..7], coalesced
        float bb = base[s] + bias[s];
#pragma unroll
        for (int tl = 0; tl < 8; tl++) {
            float acc = bb;
            acc = fmaf(m0.x, sm_mesa[0 * 8 + tl], acc);
            acc = fmaf(m0.y, sm_mesa[1 * 8 + tl], acc);
            acc = fmaf(m0.z, sm_mesa[2 * 8 + tl], acc);
            acc = fmaf(m0.w, sm_mesa[3 * 8 + tl], acc);
            acc = fmaf(m1.x, sm_mesa[4 * 8 + tl], acc);
            acc = fmaf(m1.y, sm_mesa[5 * 8 + tl], acc);
            acc = fmaf(m1.z, sm_mesa[6 * 8 + tl], acc);
            acc = fmaf(m1.w, sm_mesa[7 * 8 + tl], acc);
            st[tl * SROW + s] = acc;
        }
    }

    // ---- Global barrier (epoch-based; survives graph replays) ----
    // syncthreads + cumulative fence publishes all phase-A stores (buckets,
    // counters, out pre-seed) before the release.
    __syncthreads();
    if (tid == 0) {
        int e = *(volatile int*)&g_epoch;
        __threadfence();                    // publish block's stores (cumul.)
        int a = atomicAdd(&g_arrive, 1);
        if (a == GRID - 1) {
            g_arrive = 0;                   // restore for exit barrier
            __threadfence();
            atomicAdd(&g_epoch, 1);         // release
        } else {
            while (*(volatile int*)&g_epoch == e) __nanosleep(32);
            __threadfence();                // acquire
        }
    }
    __syncthreads();

    // ---- Phase C: 2 independent half-warps per t ----
    int t = t0 + grp;
    const float* w1 = st + grp * SROW;
    const float* b1 = w1 + 2048;
    const float* w2 = w1 + 2112;

    int cnt = g_cnt[t];                     // reset deferred to exit
    int oc = g_ocnt;
    if (cnt > CAP) cnt = CAP;
    const int* bk = g_bucket + t * CAP;

    const float* w1j = w1 + sub * 32 * DD;
    const float* b1j = b1 + sub * 32;
    const float* w2j = w2 + sub * 32;

    for (int bs = 0; bs < cnt; bs += 32) {
        int m = cnt - bs;
        if (m > 32) m = 32;
        int li = lane < m ? lane : 0;
        int n = bk[bs + li];                // coalesced bucket read

        // Per-lane x row: 8 independent LDG.128 (row = one 128B line)
        unsigned long long x2[16];
        {
            const float4* xp = (const float4*)(x + (size_t)n * DD);
#pragma unroll
            for (int k = 0; k < 8; k++) {
                float4 v = xp[k];
                PACK2(x2[2 * k],     v.x, v.y);
                PACK2(x2[2 * k + 1], v.z, v.w);
            }
        }

        float o = 0.f;
#pragma unroll 8
        for (int j = 0; j < 32; j++) {
            const ulonglong2* wr = (const ulonglong2*)(w1j + j * DD);
            unsigned long long accA = 0ull, accB = 0ull;
#pragma unroll
            for (int k = 0; k < 8; k++) {
                ulonglong2 w = wr[k];       // broadcast LDS.128
                FMA2(accA, x2[2 * k],     w.x, accA);
                FMA2(accB, x2[2 * k + 1], w.y, accB);
            }
            ADD2(accA, accA, accB);
            float a0, a1;
            UNPACK2(a0, a1, accA);
            float h = fmaxf(a0 + a1 + b1j[j], 0.f);
            o = fmaf(h, w2j[j], o);
        }
        // Combine halves: no-return REDG.F32 to distinct addresses.
        if (lane < m) atomicAdd(&out[n], o);
    }

    // ---- Overflow drain (normally oc == 0): sub==0 warp, full j range ----
    if (sub == 0) {
        for (int i = 0; i < oc; i++) {
            int n = g_ovf[i];
            if (ticker[n] == t) {
                float xr = x[n * DD + lane];
                float a0 = 0.f, a1 = 0.f;
#pragma unroll
                for (int d = 0; d < DD; d++) {
                    float xv = __shfl_sync(0xffffffffu, xr, d);
                    a0 = fmaf(w1[lane * DD + d],        xv, a0);
                    a1 = fmaf(w1[(lane + 32) * DD + d], xv, a1);
                }
                float h0 = fmaxf(a0 + b1[lane],      0.f);
                float h1 = fmaxf(a1 + b1[lane + 32], 0.f);
                float p = fmaf(h0, w2[lane], h1 * w2[lane + 32]);
#pragma unroll
                for (int off = 16; off; off >>= 1)
                    p += __shfl_down_sync(0xffffffffu, p, off);
                if (lane == 0) atomicAdd(&out[n], p);   // out has b2 already
            }
        }
    }

    // ---- Exit: restore invariants after ALL block warps finished reading ----
    __syncthreads();
    if (tid < 8) g_cnt[t0 + tid] = 0;
    if (tid == 0) {
        int a = atomicAdd(&g_arrive, 1);
        if (a == GRID - 1) { g_arrive = 0; g_ocnt = 0; }
    }
}

// ---------------------------------------------------------------------------
extern "C" void kernel_launch(void* const* d_in, const int* in_sizes, int n_in,
                              void* d_out, int out_size) {
    const float* x      = (const float*)d_in[0];
    const int*   ticker = (const int*)d_in[1];
    const float* mesa   = (const float*)d_in[2];
    const float* meta   = (const float*)d_in[3];
    const float* bias   = (const float*)d_in[4];
    const float* base   = (const float*)d_in[5];
    float* out = (float*)d_out;

    const int smem_bytes = (8 * SROW + 64) * sizeof(float);   // 70,912 B
    cudaFuncSetAttribute(fused_k, cudaFuncAttributeMaxDynamicSharedMemorySize,
                         smem_bytes);

    fused_k<<<GRID, BLOCK, smem_bytes>>>(x, ticker, mesa, meta, bias, base, out);
}

// round 15
// speedup vs baseline: 1.0734x; 1.0734x over previous
#include <cuda_runtime.h>

// Problem constants (fixed by the reference)
#define NN 32768
#define DD 32
#define HH 64
#define TT 1024
#define MM 8
#define SS 2177          // H*D + H + O*H + O
#define SROW 2208        // padded state row stride (floats)
#define CAP 128          // bucket capacity (Poisson(32); P(>128) ~ 0)
#define GRID 128         // all-resident on 148 SMs -> grid barrier is safe
#define BLOCK 256        // 8 warps: one warp per t; 2 samples per lane

// Scratch (no allocations allowed). Zero-initialized at module load; each
// launch restores the zeros it consumed (invariant across graph replays).
__device__ int g_cnt[TT];
__device__ int g_bucket[TT * CAP];
__device__ int g_ocnt;
__device__ int g_ovf[NN];
__device__ int g_arrive;
__device__ int g_epoch;     // monotonic across launches

// packed fp32x2 ops (Blackwell; ptxas never auto-fuses these)
#define FMA2(d, a, b, c) \
    asm("fma.rn.f32x2 %0, %1, %2, %3;" : "=l"(d) : "l"(a), "l"(b), "l"(c))
#define ADD2(d, a, b) \
    asm("add.rn.f32x2 %0, %1, %2;" : "=l"(d) : "l"(a), "l"(b))
#define PACK2(d, lo, hi) \
    asm("mov.b64 %0, {%1, %2};" : "=l"(d) : "f"(lo), "f"(hi))
#define UNPACK2(lo, hi, s) \
    asm("mov.b64 {%0, %1}, %2;" : "=f"(lo), "=f"(hi) : "l"(s))

// ---------------------------------------------------------------------------
// ONE fused persistent kernel.
//   Phase A: scatter n's into per-t buckets + L2-prefetch each x row.
//   Phase B: compute this block's 8 state rows straight into smem.
//   Global epoch barrier (all blocks resident).
//   Phase C: warp per t; chunks of 64 samples; lane owns TWO samples so each
//            broadcast weight LDS.128 feeds 4 independent FMA2 chains.
// ---------------------------------------------------------------------------
__global__ __launch_bounds__(BLOCK, 1)
void fused_k(const float* __restrict__ x,
             const int*   __restrict__ ticker,
             const float* __restrict__ mesa,
             const float* __restrict__ meta,
             const float* __restrict__ bias,
             const float* __restrict__ base,
             float*       __restrict__ out) {
    extern __shared__ float sm[];
    float* st      = sm;                    // 8 * SROW state rows (70.6 KB)
    float* sm_mesa = sm + 8 * SROW;         // 64 floats

    int tid  = threadIdx.x;
    int warp = tid >> 5, lane = tid & 31;
    int t0   = blockIdx.x * 8;

    // ---- Phase A: scatter + x L2 prefetch (GRID*BLOCK == NN exactly) ----
    {
        int n = blockIdx.x * BLOCK + tid;
        int t = ticker[n];
        int pos = atomicAdd(&g_cnt[t], 1);
        if (pos < CAP) g_bucket[t * CAP + pos] = n;
        else           g_ovf[atomicAdd(&g_ocnt, 1)] = n;
        // Warm L2 with this row (one 128B line) while A/B run.
        asm volatile("prefetch.global.L2 [%0];" :: "l"(x + (size_t)n * DD));
    }

    // ---- Phase B: states for my 8 t's, directly in smem ----
    if (tid < 64)
        sm_mesa[tid] = mesa[(tid >> 3) * TT + t0 + (tid & 7)];
    __syncthreads();

    for (int s = tid; s < SS; s += BLOCK) {
        const float4* mp = (const float4*)(meta + s * MM);
        float4 m0 = mp[0], m1 = mp[1];      // meta[s][0..7], coalesced
        float bb = base[s] + bias[s];
#pragma unroll
        for (int tl = 0; tl < 8; tl++) {
            float acc = bb;
            acc = fmaf(m0.x, sm_mesa[0 * 8 + tl], acc);
            acc = fmaf(m0.y, sm_mesa[1 * 8 + tl], acc);
            acc = fmaf(m0.z, sm_mesa[2 * 8 + tl], acc);
            acc = fmaf(m0.w, sm_mesa[3 * 8 + tl], acc);
            acc = fmaf(m1.x, sm_mesa[4 * 8 + tl], acc);
            acc = fmaf(m1.y, sm_mesa[5 * 8 + tl], acc);
            acc = fmaf(m1.z, sm_mesa[6 * 8 + tl], acc);
            acc = fmaf(m1.w, sm_mesa[7 * 8 + tl], acc);
            st[tl * SROW + s] = acc;
        }
    }

    // ---- Global barrier (epoch-based; survives graph replays) ----
    __syncthreads();
    if (tid == 0) {
        int e = *(volatile int*)&g_epoch;
        __threadfence();                    // publish block's stores (cumul.)
        int a = atomicAdd(&g_arrive, 1);
        if (a == GRID - 1) {
            g_arrive = 0;                   // restore for exit barrier
            __threadfence();
            atomicAdd(&g_epoch, 1);         // release
        } else {
            while (*(volatile int*)&g_epoch == e) __nanosleep(32);
            __threadfence();                // acquire
        }
    }
    __syncthreads();

    // ---- Phase C: warp per t, 2 samples per lane ----
    int t = t0 + warp;
    const float* w1 = st + warp * SROW;
    const float* b1 = w1 + 2048;
    const float* w2 = w1 + 2112;
    float b2v = w1[2176];

    int cnt = g_cnt[t];
    if (lane == 0) g_cnt[t] = 0;            // restore invariant (program order)
    int oc = g_ocnt;
    if (cnt > CAP) cnt = CAP;
    const int* bk = g_bucket + t * CAP;

    for (int bs = 0; bs < cnt; bs += 64) {
        int m  = cnt - bs;  if (m > 64) m = 64;
        int mA = m < 32 ? m : 32;           // samples in slot A
        int liA = lane < mA ? lane : 0;
        int liB = (32 + lane) < m ? (32 + lane) : liA;
        int nA = bk[bs + liA];
        int nB = bk[bs + liB];

        // Two per-lane x rows: 16 independent LDG.128 (row = one 128B line)
        unsigned long long xa[16], xb[16];
        {
            const float4* pa = (const float4*)(x + (size_t)nA * DD);
            const float4* pb = (const float4*)(x + (size_t)nB * DD);
#pragma unroll
            for (int k = 0; k < 8; k++) {
                float4 va = pa[k];
                float4 vb = pb[k];
                PACK2(xa[2 * k],     va.x, va.y);
                PACK2(xa[2 * k + 1], va.z, va.w);
                PACK2(xb[2 * k],     vb.x, vb.y);
                PACK2(xb[2 * k + 1], vb.z, vb.w);
            }
        }

        float oA = 0.f, oB = 0.f;
#pragma unroll 4
        for (int j = 0; j < HH; j++) {
            const ulonglong2* wr = (const ulonglong2*)(w1 + j * DD);
            unsigned long long aA0 = 0ull, aA1 = 0ull;   // 4 independent
            unsigned long long aB0 = 0ull, aB1 = 0ull;   // FMA2 chains
#pragma unroll
            for (int k = 0; k < 8; k++) {
                ulonglong2 w = wr[k];       // ONE broadcast LDS.128, 4 uses
                FMA2(aA0, xa[2 * k],     w.x, aA0);
                FMA2(aA1, xa[2 * k + 1], w.y, aA1);
                FMA2(aB0, xb[2 * k],     w.x, aB0);
                FMA2(aB1, xb[2 * k + 1], w.y, aB1);
            }
            ADD2(aA0, aA0, aA1);
            ADD2(aB0, aB0, aB1);
            float u0, u1, v0, v1;
            UNPACK2(u0, u1, aA0);
            UNPACK2(v0, v1, aB0);
            float bj = b1[j], w2j = w2[j];
            float hA = fmaxf(u0 + u1 + bj, 0.f);
            float hB = fmaxf(v0 + v1 + bj, 0.f);
            oA = fmaf(hA, w2j, oA);
            oB = fmaf(hB, w2j, oB);
        }
        if (lane < mA)      out[nA] = oA + b2v;
        if (32 + lane < m)  out[nB] = oB + b2v;
    }

    // ---- Overflow drain (normally oc == 0): warp-cooperative path ----
    for (int i = 0; i < oc; i++) {
        int n = g_ovf[i];
        if (ticker[n] == t) {
            float xr = x[n * DD + lane];
            float a0 = 0.f, a1 = 0.f;
#pragma unroll
            for (int d = 0; d < DD; d++) {
                float xv = __shfl_sync(0xffffffffu, xr, d);
                a0 = fmaf(w1[lane * DD + d],        xv, a0);
                a1 = fmaf(w1[(lane + 32) * DD + d], xv, a1);
            }
            float h0 = fmaxf(a0 + b1[lane],      0.f);
            float h1 = fmaxf(a1 + b1[lane + 32], 0.f);
            float p = fmaf(h0, w2[lane], h1 * w2[lane + 32]);
#pragma unroll
            for (int off = 16; off; off >>= 1)
                p += __shfl_down_sync(0xffffffffu, p, off);
            if (lane == 0) out[n] = p + b2v;
        }
    }

    // ---- Exit barrier (arrive-only): last block restores g_ocnt ----
    __syncthreads();
    if (tid == 0) {
        int a = atomicAdd(&g_arrive, 1);
        if (a == GRID - 1) { g_arrive = 0; g_ocnt = 0; }
    }
}

// ---------------------------------------------------------------------------
extern "C" void kernel_launch(void* const* d_in, const int* in_sizes, int n_in,
                              void* d_out, int out_size) {
    const float* x      = (const float*)d_in[0];
    const int*   ticker = (const int*)d_in[1];
    const float* mesa   = (const float*)d_in[2];
    const float* meta   = (const float*)d_in[3];
    const float* bias   = (const float*)d_in[4];
    const float* base   = (const float*)d_in[5];
    float* out = (float*)d_out;

    const int smem_bytes = (8 * SROW + 64) * sizeof(float);   // 70,912 B
    cudaFuncSetAttribute(fused_k, cudaFuncAttributeMaxDynamicSharedMemorySize,
                         smem_bytes);

    fused_k<<<GRID, BLOCK, smem_bytes>>>(x, ticker, mesa, meta, bias, base, out);
}